// round 11
// baseline (speedup 1.0000x reference)
#include <cuda_runtime.h>
#include <cstdint>

#define NUM_LABELS 64
#define RED_CTAS 444                 // 3 CTAs per SM * 148 SMs
#define RED_THREADS 256

// Scratch (allocation-free rule: __device__ globals)
__device__ float  g_sums[NUM_LABELS];     // fallback path only
__device__ float  g_cnts[NUM_LABELS];     // fallback path only
__device__ float  g_delta[NUM_LABELS];
__device__ float2 g_part[RED_CTAS][NUM_LABELS];   // per-CTA partials (fast path)

// ---------------------------------------------------------------------------
// Kernel 1 (fast): per-label sum+count, no atomics, 4-byte bias-packed slots:
//   slot += fmaf(v, 2^-12, 1.0f)  -> integer part = count, frac*4096 = sum.
// Table acc[label*256 + tid]: 64KB smem, 3 CTAs/SM, conflict-free.
// Software-pipelined (UNROLL 3).
//
// ROUND-11 CACHE PLAN: labels are the ONE L2-resident stream (__ldcg,
// 100.7MB < 126MB L2, nothing else uses normal policy); tex evict-first.
// NO lab8 scratch anymore — reduce is a pure read kernel (no store
// backpressure, no gpu-scope fence), and apply re-reads labels from L2.
// Total DRAM drops ~450 -> ~401 MB.
//
// Delta computed by a separate tiny kernel (round-10 showed the fused
// last-CTA fence costs ~5us after heavy streaming stores; even though
// reduce now has no big stores, the separate kernel is proven and cheap).
// ---------------------------------------------------------------------------
#define BIAS_SCALE (1.0f / 4096.0f)
#define UNROLL 3

__global__ void __launch_bounds__(RED_THREADS, 3)
reduce_k(const float4* __restrict__ tex4, const int4* __restrict__ lab4, int n4) {
    extern __shared__ float acc[];   // [64][256]
    const int tid = threadIdx.x;

    #pragma unroll
    for (int i = tid; i < NUM_LABELS * RED_THREADS; i += RED_THREADS)
        acc[i] = 0.0f;
    __syncthreads();

    const int stride = gridDim.x * RED_THREADS;
    int i = blockIdx.x * RED_THREADS + tid;

    float4 t[UNROLL];
    int4   l[UNROLL];
    bool have = (i + (UNROLL - 1) * stride < n4);
    if (have) {
        #pragma unroll
        for (int u = 0; u < UNROLL; u++) t[u] = __ldcs(&tex4[i + u * stride]);
        #pragma unroll
        for (int u = 0; u < UNROLL; u++) l[u] = __ldcg(&lab4[i + u * stride]);
    }

    while (have) {
        int inext = i + UNROLL * stride;
        bool have_next = (inext + (UNROLL - 1) * stride < n4);

        float4 t2[UNROLL];
        int4   l2[UNROLL];
        if (have_next) {   // issue next loads BEFORE the RMW chain
            #pragma unroll
            for (int u = 0; u < UNROLL; u++) t2[u] = __ldcs(&tex4[inext + u * stride]);
            #pragma unroll
            for (int u = 0; u < UNROLL; u++) l2[u] = __ldcg(&lab4[inext + u * stride]);
        }

        #pragma unroll
        for (int u = 0; u < UNROLL; u++) {
            acc[l[u].x * RED_THREADS + tid] += fmaf(t[u].x, BIAS_SCALE, 1.0f);
            acc[l[u].y * RED_THREADS + tid] += fmaf(t[u].y, BIAS_SCALE, 1.0f);
            acc[l[u].z * RED_THREADS + tid] += fmaf(t[u].z, BIAS_SCALE, 1.0f);
            acc[l[u].w * RED_THREADS + tid] += fmaf(t[u].w, BIAS_SCALE, 1.0f);
        }

        #pragma unroll
        for (int u = 0; u < UNROLL; u++) { t[u] = t2[u]; l[u] = l2[u]; }
        i = inext;
        have = have_next;
    }

    // residue (fewer than UNROLL strides left)
    for (; i < n4; i += stride) {
        const float4 tt = __ldcs(&tex4[i]);
        const int4   ll = __ldcg(&lab4[i]);
        acc[ll.x * RED_THREADS + tid] += fmaf(tt.x, BIAS_SCALE, 1.0f);
        acc[ll.y * RED_THREADS + tid] += fmaf(tt.y, BIAS_SCALE, 1.0f);
        acc[ll.z * RED_THREADS + tid] += fmaf(tt.z, BIAS_SCALE, 1.0f);
        acc[ll.w * RED_THREADS + tid] += fmaf(tt.w, BIAS_SCALE, 1.0f);
    }
    __syncthreads();

    // Epilogue: thread l < 64 decodes its label's 256 slots -> per-CTA partial.
    if (tid < NUM_LABELS) {
        float s = 0.0f, c = 0.0f;
        #pragma unroll 8
        for (int k = 0; k < RED_THREADS; k++) {
            int sp = (k + tid) & (RED_THREADS - 1);
            float a = acc[tid * RED_THREADS + sp];
            float cnt = rintf(a);
            s += (a - cnt) * 4096.0f;
            c += cnt;
        }
        g_part[blockIdx.x][tid] = make_float2(s, c);   // plain store, no atomics
    }
}

// ---------------------------------------------------------------------------
// Kernel 2 (fast): block per label reduces 444 partials -> delta
// ---------------------------------------------------------------------------
__global__ void __launch_bounds__(128) delta_fast_k(const float* __restrict__ inten) {
    __shared__ float sh_s[4], sh_c[4];
    const int l = blockIdx.x;
    const int tid = threadIdx.x;

    float s = 0.0f, c = 0.0f;
    for (int p = tid; p < RED_CTAS; p += 128) {
        float2 v = g_part[p][l];
        s += v.x; c += v.y;
    }
    #pragma unroll
    for (int o = 16; o > 0; o >>= 1) {
        s += __shfl_down_sync(0xFFFFFFFF, s, o);
        c += __shfl_down_sync(0xFFFFFFFF, c, o);
    }
    if ((tid & 31) == 0) { sh_s[tid >> 5] = s; sh_c[tid >> 5] = c; }
    __syncthreads();
    if (tid == 0) {
        s = sh_s[0] + sh_s[1] + sh_s[2] + sh_s[3];
        c = sh_c[0] + sh_c[1] + sh_c[2] + sh_c[3];
        float m = s / fmaxf(c, 1.0f);
        g_delta[l] = (l > 0) ? (m - inten[l]) : 0.0f;
    }
}

// ---------------------------------------------------------------------------
// Kernel 3 (fast): out = tex - delta[lab], 2 tiles per thread.
// Labels via __ldcg -> expected L2 HITS (left resident by reduce_k);
// tex evict-first (single use), out evict-first (write-once).
// ---------------------------------------------------------------------------
__global__ void __launch_bounds__(256) apply_k(const float4* __restrict__ tex4,
                                               const int4* __restrict__ lab4,
                                               float4* __restrict__ out4,
                                               int n4) {
    __shared__ float sd[NUM_LABELS];
    if (threadIdx.x < NUM_LABELS) sd[threadIdx.x] = g_delta[threadIdx.x];
    __syncthreads();

    int i0 = blockIdx.x * 512 + threadIdx.x;
    int i1 = i0 + 256;

    if (i1 < n4) {
        const float4 ta = __ldcs(&tex4[i0]);
        const float4 tb = __ldcs(&tex4[i1]);
        const int4   la = __ldcg(&lab4[i0]);
        const int4   lb = __ldcg(&lab4[i1]);
        float4 oa, ob;
        oa.x = ta.x - sd[la.x];
        oa.y = ta.y - sd[la.y];
        oa.z = ta.z - sd[la.z];
        oa.w = ta.w - sd[la.w];
        ob.x = tb.x - sd[lb.x];
        ob.y = tb.y - sd[lb.y];
        ob.z = tb.z - sd[lb.z];
        ob.w = tb.w - sd[lb.w];
        __stcs(&out4[i0], oa);
        __stcs(&out4[i1], ob);
    } else if (i0 < n4) {
        const float4 t = __ldcs(&tex4[i0]);
        const int4   l = __ldcg(&lab4[i0]);
        float4 o;
        o.x = t.x - sd[l.x];
        o.y = t.y - sd[l.y];
        o.z = t.z - sd[l.z];
        o.w = t.w - sd[l.w];
        __stcs(&out4[i0], o);
    }
}

// ---------------------------------------------------------------------------
// Fallback path (n not 4-divisible): scalar, shared-atomic
// ---------------------------------------------------------------------------
__global__ void zero_k() {
    int i = threadIdx.x;
    if (i < NUM_LABELS) { g_sums[i] = 0.0f; g_cnts[i] = 0.0f; }
}

__global__ void __launch_bounds__(256) reduce_scalar_k(const float* __restrict__ tex,
                                                       const int*  __restrict__ lab,
                                                       int n) {
    __shared__ float2 accw[8][NUM_LABELS];
    const int w = threadIdx.x >> 5;
    for (int i = threadIdx.x; i < 8 * NUM_LABELS; i += 256)
        (&accw[0][0])[i] = make_float2(0.0f, 0.0f);
    __syncthreads();
    int i = blockIdx.x * 256 + threadIdx.x;
    const int stride = gridDim.x * 256;
    for (; i < n; i += stride) {
        atomicAdd(&accw[w][lab[i]].x, tex[i]);
        atomicAdd(&accw[w][lab[i]].y, 1.0f);
    }
    __syncthreads();
    for (int l = threadIdx.x; l < NUM_LABELS; l += 256) {
        float s = 0.0f, c = 0.0f;
        #pragma unroll
        for (int ww = 0; ww < 8; ww++) { s += accw[ww][l].x; c += accw[ww][l].y; }
        atomicAdd(&g_sums[l], s);
        atomicAdd(&g_cnts[l], c);
    }
}

__global__ void delta_k(const float* __restrict__ inten) {
    int l = threadIdx.x;
    if (l < NUM_LABELS) {
        float m = g_sums[l] / fmaxf(g_cnts[l], 1.0f);
        g_delta[l] = (l > 0) ? (m - inten[l]) : 0.0f;
    }
}

__global__ void __launch_bounds__(256) apply_scalar_k(const float* __restrict__ tex,
                                                      const int*  __restrict__ lab,
                                                      float* __restrict__ out,
                                                      int n) {
    __shared__ float sd[NUM_LABELS];
    if (threadIdx.x < NUM_LABELS) sd[threadIdx.x] = g_delta[threadIdx.x];
    __syncthreads();
    int i = blockIdx.x * 256 + threadIdx.x;
    if (i < n) out[i] = tex[i] - sd[lab[i]];
}

// ---------------------------------------------------------------------------
extern "C" void kernel_launch(void* const* d_in, const int* in_sizes, int n_in,
                              void* d_out, int out_size) {
    const float* tex   = (const float*)d_in[0];
    const int*   lab   = (const int*)  d_in[1];
    const float* inten = (const float*)d_in[2];
    float* out = (float*)d_out;

    const int n  = in_sizes[0];
    const int n4 = n >> 2;
    const bool fast = ((n & 3) == 0) && (n4 >= RED_CTAS * RED_THREADS);

    if (fast) {
        static int smem_set = 0;   // host-side one-time config
        const int smem_bytes = NUM_LABELS * RED_THREADS * (int)sizeof(float); // 64KB
        if (!smem_set) {
            cudaFuncSetAttribute(reduce_k, cudaFuncAttributeMaxDynamicSharedMemorySize,
                                 smem_bytes);
            smem_set = 1;
        }
        reduce_k<<<RED_CTAS, RED_THREADS, smem_bytes>>>((const float4*)tex,
                                                        (const int4*)lab, n4);
        delta_fast_k<<<NUM_LABELS, 128>>>(inten);
        int app_blocks = (n4 + 511) / 512;
        apply_k<<<app_blocks, 256>>>((const float4*)tex, (const int4*)lab,
                                     (float4*)out, n4);
    } else {
        zero_k<<<1, 64>>>();
        reduce_scalar_k<<<1184, 256>>>(tex, lab, n);
        delta_k<<<1, 64>>>(inten);
        int app_blocks = (n + 255) / 256;
        apply_scalar_k<<<app_blocks, 256>>>(tex, lab, out, n);
    }
}

// round 12
// speedup vs baseline: 1.1137x; 1.1137x over previous
#include <cuda_runtime.h>
#include <cstdint>

#define NUM_LABELS 64
#define MAXN (2 * 192 * 256 * 256)   // 25,165,824 — reference shape
#define RED_CTAS 444                 // 3 CTAs per SM * 148 SMs
#define RED_THREADS 256

// Scratch (allocation-free rule: __device__ globals)
__device__ float  g_sums[NUM_LABELS];     // fallback path only
__device__ float  g_cnts[NUM_LABELS];     // fallback path only
__device__ float  g_delta[NUM_LABELS];
__device__ float2 g_part[RED_CTAS][NUM_LABELS];   // per-CTA partials (fast path)
__device__ unsigned char g_lab8[MAXN];    // compressed labels for the apply pass

// ---------------------------------------------------------------------------
// Kernel 1 (fast): per-label sum+count, no atomics, 4-byte bias-packed slots:
//   slot += fmaf(v, 2^-12, 1.0f)  -> integer part = count, frac*4096 = sum.
// Table acc[label*256 + tid]: 64KB smem, 3 CTAs/SM, conflict-free.
//
// ROUND-12 CHANGE: contiguous per-CTA chunks (~227KB) instead of grid-stride.
// Grid-stride hopped ~1.8MB per warp-iteration (new DRAM row + TLB page per
// 512B); chunking keeps every CTA inside a 2MB page with long same-row
// bursts on tex/lab/lab8 -> higher DRAM efficiency.
//
// CACHE PLAN (round-8 proven): tex/lab evict-first (__ldcs); lab8 __stcg so
// its 25MB survives in L2 for apply (protected because everything else is
// evict-first). Round-11 proved 100MB streams CANNOT be carried across
// kernels in L2 (sequential eviction leaves the wrong end resident).
// ---------------------------------------------------------------------------
#define BIAS_SCALE (1.0f / 4096.0f)
#define UNROLL 3

__global__ void __launch_bounds__(RED_THREADS, 3)
reduce_k(const float4* __restrict__ tex4, const int4* __restrict__ lab4, int n4) {
    extern __shared__ float acc[];   // [64][256]
    const int tid = threadIdx.x;

    #pragma unroll
    for (int i = tid; i < NUM_LABELS * RED_THREADS; i += RED_THREADS)
        acc[i] = 0.0f;
    __syncthreads();

    unsigned int* lab8w = (unsigned int*)g_lab8;

    // contiguous chunk for this CTA
    const int per   = (n4 + gridDim.x - 1) / gridDim.x;
    const int start = blockIdx.x * per;
    const int end   = (start + per < n4) ? (start + per) : n4;
    const int stride = RED_THREADS;           // within-chunk stride

    int i = start + tid;

    float4 t[UNROLL];
    int4   l[UNROLL];
    bool have = (i + (UNROLL - 1) * stride < end);
    if (have) {
        #pragma unroll
        for (int u = 0; u < UNROLL; u++) t[u] = __ldcs(&tex4[i + u * stride]);
        #pragma unroll
        for (int u = 0; u < UNROLL; u++) l[u] = __ldcs(&lab4[i + u * stride]);
    }

    while (have) {
        const int icur = i;
        int inext = i + UNROLL * stride;
        bool have_next = (inext + (UNROLL - 1) * stride < end);

        float4 t2[UNROLL];
        int4   l2[UNROLL];
        if (have_next) {   // issue next loads BEFORE the RMW chain
            #pragma unroll
            for (int u = 0; u < UNROLL; u++) t2[u] = __ldcs(&tex4[inext + u * stride]);
            #pragma unroll
            for (int u = 0; u < UNROLL; u++) l2[u] = __ldcs(&lab4[inext + u * stride]);
        }

        #pragma unroll
        for (int u = 0; u < UNROLL; u++) {
            __stcg(&lab8w[icur + u * stride],
                   (unsigned)l[u].x | ((unsigned)l[u].y << 8) |
                   ((unsigned)l[u].z << 16) | ((unsigned)l[u].w << 24));
            acc[l[u].x * RED_THREADS + tid] += fmaf(t[u].x, BIAS_SCALE, 1.0f);
            acc[l[u].y * RED_THREADS + tid] += fmaf(t[u].y, BIAS_SCALE, 1.0f);
            acc[l[u].z * RED_THREADS + tid] += fmaf(t[u].z, BIAS_SCALE, 1.0f);
            acc[l[u].w * RED_THREADS + tid] += fmaf(t[u].w, BIAS_SCALE, 1.0f);
        }

        #pragma unroll
        for (int u = 0; u < UNROLL; u++) { t[u] = t2[u]; l[u] = l2[u]; }
        i = inext;
        have = have_next;
    }

    // residue (fewer than UNROLL strides left in chunk)
    for (; i < end; i += stride) {
        const float4 tt = __ldcs(&tex4[i]);
        const int4   ll = __ldcs(&lab4[i]);
        __stcg(&lab8w[i], (unsigned)ll.x | ((unsigned)ll.y << 8) |
                          ((unsigned)ll.z << 16) | ((unsigned)ll.w << 24));
        acc[ll.x * RED_THREADS + tid] += fmaf(tt.x, BIAS_SCALE, 1.0f);
        acc[ll.y * RED_THREADS + tid] += fmaf(tt.y, BIAS_SCALE, 1.0f);
        acc[ll.z * RED_THREADS + tid] += fmaf(tt.z, BIAS_SCALE, 1.0f);
        acc[ll.w * RED_THREADS + tid] += fmaf(tt.w, BIAS_SCALE, 1.0f);
    }
    __syncthreads();

    // Epilogue: thread l < 64 decodes its label's 256 slots -> per-CTA partial.
    if (tid < NUM_LABELS) {
        float s = 0.0f, c = 0.0f;
        #pragma unroll 8
        for (int k = 0; k < RED_THREADS; k++) {
            int sp = (k + tid) & (RED_THREADS - 1);
            float a = acc[tid * RED_THREADS + sp];
            float cnt = rintf(a);
            s += (a - cnt) * 4096.0f;
            c += cnt;
        }
        g_part[blockIdx.x][tid] = make_float2(s, c);   // plain store, no atomics
    }
}

// ---------------------------------------------------------------------------
// Kernel 2 (fast): block per label reduces 444 partials -> delta
// ---------------------------------------------------------------------------
__global__ void __launch_bounds__(128) delta_fast_k(const float* __restrict__ inten) {
    __shared__ float sh_s[4], sh_c[4];
    const int l = blockIdx.x;
    const int tid = threadIdx.x;

    float s = 0.0f, c = 0.0f;
    for (int p = tid; p < RED_CTAS; p += 128) {
        float2 v = g_part[p][l];
        s += v.x; c += v.y;
    }
    #pragma unroll
    for (int o = 16; o > 0; o >>= 1) {
        s += __shfl_down_sync(0xFFFFFFFF, s, o);
        c += __shfl_down_sync(0xFFFFFFFF, c, o);
    }
    if ((tid & 31) == 0) { sh_s[tid >> 5] = s; sh_c[tid >> 5] = c; }
    __syncthreads();
    if (tid == 0) {
        s = sh_s[0] + sh_s[1] + sh_s[2] + sh_s[3];
        c = sh_c[0] + sh_c[1] + sh_c[2] + sh_c[3];
        float m = s / fmaxf(c, 1.0f);
        g_delta[l] = (l > 0) ? (m - inten[l]) : 0.0f;
    }
}

// ---------------------------------------------------------------------------
// Kernel 3 (fast): out = tex - delta[lab8], 2 float4 tiles per thread.
// tex evict-first (single use), out evict-first (write-once),
// lab8 via __ldcg (L2-resident from reduce's __stcg; skip L1).
// ---------------------------------------------------------------------------
__global__ void __launch_bounds__(256) apply_packed_k(const float4* __restrict__ tex4,
                                                      float4* __restrict__ out4,
                                                      int n4) {
    __shared__ float sd[NUM_LABELS];
    if (threadIdx.x < NUM_LABELS) sd[threadIdx.x] = g_delta[threadIdx.x];
    __syncthreads();

    const unsigned int* lab8w = (const unsigned int*)g_lab8;
    int i0 = blockIdx.x * 512 + threadIdx.x;
    int i1 = i0 + 256;

    if (i1 < n4) {
        const float4 ta = __ldcs(&tex4[i0]);
        const float4 tb = __ldcs(&tex4[i1]);
        const unsigned int la = __ldcg(&lab8w[i0]);
        const unsigned int lb = __ldcg(&lab8w[i1]);
        float4 oa, ob;
        oa.x = ta.x - sd[la & 0xFF];
        oa.y = ta.y - sd[(la >> 8) & 0xFF];
        oa.z = ta.z - sd[(la >> 16) & 0xFF];
        oa.w = ta.w - sd[la >> 24];
        ob.x = tb.x - sd[lb & 0xFF];
        ob.y = tb.y - sd[(lb >> 8) & 0xFF];
        ob.z = tb.z - sd[(lb >> 16) & 0xFF];
        ob.w = tb.w - sd[lb >> 24];
        __stcs(&out4[i0], oa);
        __stcs(&out4[i1], ob);
    } else if (i0 < n4) {
        const float4 t = __ldcs(&tex4[i0]);
        const unsigned int l = __ldcg(&lab8w[i0]);
        float4 o;
        o.x = t.x - sd[l & 0xFF];
        o.y = t.y - sd[(l >> 8) & 0xFF];
        o.z = t.z - sd[(l >> 16) & 0xFF];
        o.w = t.w - sd[l >> 24];
        __stcs(&out4[i0], o);
    }
}

// ---------------------------------------------------------------------------
// Fallback path (n not 4-divisible or > MAXN): scalar, shared-atomic
// ---------------------------------------------------------------------------
__global__ void zero_k() {
    int i = threadIdx.x;
    if (i < NUM_LABELS) { g_sums[i] = 0.0f; g_cnts[i] = 0.0f; }
}

__global__ void __launch_bounds__(256) reduce_scalar_k(const float* __restrict__ tex,
                                                       const int*  __restrict__ lab,
                                                       int n) {
    __shared__ float2 accw[8][NUM_LABELS];
    const int w = threadIdx.x >> 5;
    for (int i = threadIdx.x; i < 8 * NUM_LABELS; i += 256)
        (&accw[0][0])[i] = make_float2(0.0f, 0.0f);
    __syncthreads();
    int i = blockIdx.x * 256 + threadIdx.x;
    const int stride = gridDim.x * 256;
    for (; i < n; i += stride) {
        atomicAdd(&accw[w][lab[i]].x, tex[i]);
        atomicAdd(&accw[w][lab[i]].y, 1.0f);
    }
    __syncthreads();
    for (int l = threadIdx.x; l < NUM_LABELS; l += 256) {
        float s = 0.0f, c = 0.0f;
        #pragma unroll
        for (int ww = 0; ww < 8; ww++) { s += accw[ww][l].x; c += accw[ww][l].y; }
        atomicAdd(&g_sums[l], s);
        atomicAdd(&g_cnts[l], c);
    }
}

__global__ void delta_k(const float* __restrict__ inten) {
    int l = threadIdx.x;
    if (l < NUM_LABELS) {
        float m = g_sums[l] / fmaxf(g_cnts[l], 1.0f);
        g_delta[l] = (l > 0) ? (m - inten[l]) : 0.0f;
    }
}

__global__ void __launch_bounds__(256) apply_scalar_k(const float* __restrict__ tex,
                                                      const int*  __restrict__ lab,
                                                      float* __restrict__ out,
                                                      int n) {
    __shared__ float sd[NUM_LABELS];
    if (threadIdx.x < NUM_LABELS) sd[threadIdx.x] = g_delta[threadIdx.x];
    __syncthreads();
    int i = blockIdx.x * 256 + threadIdx.x;
    if (i < n) out[i] = tex[i] - sd[lab[i]];
}

// ---------------------------------------------------------------------------
extern "C" void kernel_launch(void* const* d_in, const int* in_sizes, int n_in,
                              void* d_out, int out_size) {
    const float* tex   = (const float*)d_in[0];
    const int*   lab   = (const int*)  d_in[1];
    const float* inten = (const float*)d_in[2];
    float* out = (float*)d_out;

    const int n  = in_sizes[0];
    const int n4 = n >> 2;
    const bool fast = ((n & 3) == 0) && (n <= MAXN) && (n4 >= RED_CTAS * RED_THREADS);

    if (fast) {
        static int smem_set = 0;   // host-side one-time config
        const int smem_bytes = NUM_LABELS * RED_THREADS * (int)sizeof(float); // 64KB
        if (!smem_set) {
            cudaFuncSetAttribute(reduce_k, cudaFuncAttributeMaxDynamicSharedMemorySize,
                                 smem_bytes);
            smem_set = 1;
        }
        reduce_k<<<RED_CTAS, RED_THREADS, smem_bytes>>>((const float4*)tex,
                                                        (const int4*)lab, n4);
        delta_fast_k<<<NUM_LABELS, 128>>>(inten);
        int app_blocks = (n4 + 511) / 512;
        apply_packed_k<<<app_blocks, 256>>>((const float4*)tex, (float4*)out, n4);
    } else {
        zero_k<<<1, 64>>>();
        reduce_scalar_k<<<1184, 256>>>(tex, lab, n);
        delta_k<<<1, 64>>>(inten);
        int app_blocks = (n + 255) / 256;
        apply_scalar_k<<<app_blocks, 256>>>(tex, lab, out, n);
    }
}

// round 13
// speedup vs baseline: 1.1694x; 1.0500x over previous
#include <cuda_runtime.h>
#include <cstdint>

#define NUM_LABELS 64
#define MAXN (2 * 192 * 256 * 256)   // 25,165,824 — reference shape
#define RED_CTAS 444                 // 3 CTAs per SM * 148 SMs
#define RED_THREADS 256

// Scratch (allocation-free rule: __device__ globals)
__device__ float  g_sums[NUM_LABELS];     // fallback path only
__device__ float  g_cnts[NUM_LABELS];     // fallback path only
__device__ float  g_delta[NUM_LABELS];
__device__ float2 g_part[RED_CTAS][NUM_LABELS];   // per-CTA partials (fast path)
__device__ unsigned char g_lab8[MAXN];    // compressed labels for the apply pass

// ---------------------------------------------------------------------------
// Kernel 1 (fast): per-label sum+count, no atomics, 4-byte bias-packed slots:
//   slot += fmaf(v, 2^-12, 1.0f)  -> integer part = count, frac*4096 = sum.
// Table acc[label*256 + tid]: 64KB smem, 3 CTAs/SM, conflict-free.
// GRID-STRIDE (round-12 proved contiguous chunking is WORSE: 444 independent
// streams defeat channel interleaving; grid-stride keeps one coherent global
// wavefront). Software-pipelined, UNROLL 3.
//
// CACHE PLAN (round-8 proven optimum): tex/lab evict-first (__ldcs); lab8
// __stcg so its 25MB survives in L2 for apply. 100MB streams cannot be
// carried across kernels (round 9/11); fused-delta fence costs ~5us after
// streaming stores (round 10).
//
// Epilogue parallelized 4x vs round 8: all 256 threads decode (thread t ->
// label t&63, quarter t>>6), then 4-way combine through smem.
// ---------------------------------------------------------------------------
#define BIAS_SCALE (1.0f / 4096.0f)
#define UNROLL 3

__global__ void __launch_bounds__(RED_THREADS, 3)
reduce_k(const float4* __restrict__ tex4, const int4* __restrict__ lab4, int n4) {
    extern __shared__ float acc[];   // [64][256]
    const int tid = threadIdx.x;

    #pragma unroll
    for (int i = tid; i < NUM_LABELS * RED_THREADS; i += RED_THREADS)
        acc[i] = 0.0f;
    __syncthreads();

    unsigned int* lab8w = (unsigned int*)g_lab8;

    const int stride = gridDim.x * RED_THREADS;
    int i = blockIdx.x * RED_THREADS + tid;

    float4 t[UNROLL];
    int4   l[UNROLL];
    bool have = (i + (UNROLL - 1) * stride < n4);
    if (have) {
        #pragma unroll
        for (int u = 0; u < UNROLL; u++) t[u] = __ldcs(&tex4[i + u * stride]);
        #pragma unroll
        for (int u = 0; u < UNROLL; u++) l[u] = __ldcs(&lab4[i + u * stride]);
    }

    while (have) {
        const int icur = i;
        int inext = i + UNROLL * stride;
        bool have_next = (inext + (UNROLL - 1) * stride < n4);

        float4 t2[UNROLL];
        int4   l2[UNROLL];
        if (have_next) {   // issue next loads BEFORE the RMW chain
            #pragma unroll
            for (int u = 0; u < UNROLL; u++) t2[u] = __ldcs(&tex4[inext + u * stride]);
            #pragma unroll
            for (int u = 0; u < UNROLL; u++) l2[u] = __ldcs(&lab4[inext + u * stride]);
        }

        #pragma unroll
        for (int u = 0; u < UNROLL; u++) {
            __stcg(&lab8w[icur + u * stride],
                   (unsigned)l[u].x | ((unsigned)l[u].y << 8) |
                   ((unsigned)l[u].z << 16) | ((unsigned)l[u].w << 24));
            acc[l[u].x * RED_THREADS + tid] += fmaf(t[u].x, BIAS_SCALE, 1.0f);
            acc[l[u].y * RED_THREADS + tid] += fmaf(t[u].y, BIAS_SCALE, 1.0f);
            acc[l[u].z * RED_THREADS + tid] += fmaf(t[u].z, BIAS_SCALE, 1.0f);
            acc[l[u].w * RED_THREADS + tid] += fmaf(t[u].w, BIAS_SCALE, 1.0f);
        }

        #pragma unroll
        for (int u = 0; u < UNROLL; u++) { t[u] = t2[u]; l[u] = l2[u]; }
        i = inext;
        have = have_next;
    }

    // residue (fewer than UNROLL strides left)
    for (; i < n4; i += stride) {
        const float4 tt = __ldcs(&tex4[i]);
        const int4   ll = __ldcs(&lab4[i]);
        __stcg(&lab8w[i], (unsigned)ll.x | ((unsigned)ll.y << 8) |
                          ((unsigned)ll.z << 16) | ((unsigned)ll.w << 24));
        acc[ll.x * RED_THREADS + tid] += fmaf(tt.x, BIAS_SCALE, 1.0f);
        acc[ll.y * RED_THREADS + tid] += fmaf(tt.y, BIAS_SCALE, 1.0f);
        acc[ll.z * RED_THREADS + tid] += fmaf(tt.z, BIAS_SCALE, 1.0f);
        acc[ll.w * RED_THREADS + tid] += fmaf(tt.w, BIAS_SCALE, 1.0f);
    }
    __syncthreads();

    // Parallel epilogue: thread t decodes quarter (t>>6) of label (t&63).
    {
        const int lbl = tid & 63;
        const int quarter = tid >> 6;            // 0..3
        const int base = lbl * RED_THREADS + quarter * 64;
        float s = 0.0f, c = 0.0f;
        #pragma unroll 8
        for (int k = 0; k < 64; k++) {
            int sp = (k + tid) & 63;             // staggered, conflict-free
            float a = acc[base + sp];
            float cnt = rintf(a);                // exact count (|frac| < 0.5)
            s += (a - cnt) * 4096.0f;
            c += cnt;
        }
        __syncthreads();                          // all reads done before overwrite
        acc[quarter * 64 + lbl] = s;              // reuse table as scratch
        acc[256 + quarter * 64 + lbl] = c;
        __syncthreads();
        if (tid < NUM_LABELS) {
            float S = acc[tid] + acc[64 + tid] + acc[128 + tid] + acc[192 + tid];
            float C = acc[256 + tid] + acc[320 + tid] + acc[384 + tid] + acc[448 + tid];
            g_part[blockIdx.x][tid] = make_float2(S, C);   // plain store, no atomics
        }
    }
}

// ---------------------------------------------------------------------------
// Kernel 2 (fast): block per label reduces 444 partials -> delta
// ---------------------------------------------------------------------------
__global__ void __launch_bounds__(128) delta_fast_k(const float* __restrict__ inten) {
    __shared__ float sh_s[4], sh_c[4];
    const int l = blockIdx.x;
    const int tid = threadIdx.x;

    float s = 0.0f, c = 0.0f;
    for (int p = tid; p < RED_CTAS; p += 128) {
        float2 v = g_part[p][l];
        s += v.x; c += v.y;
    }
    #pragma unroll
    for (int o = 16; o > 0; o >>= 1) {
        s += __shfl_down_sync(0xFFFFFFFF, s, o);
        c += __shfl_down_sync(0xFFFFFFFF, c, o);
    }
    if ((tid & 31) == 0) { sh_s[tid >> 5] = s; sh_c[tid >> 5] = c; }
    __syncthreads();
    if (tid == 0) {
        s = sh_s[0] + sh_s[1] + sh_s[2] + sh_s[3];
        c = sh_c[0] + sh_c[1] + sh_c[2] + sh_c[3];
        float m = s / fmaxf(c, 1.0f);
        g_delta[l] = (l > 0) ? (m - inten[l]) : 0.0f;
    }
}

// ---------------------------------------------------------------------------
// Kernel 3 (fast): out = tex - delta[lab8], 2 float4 tiles per thread.
// tex evict-first (single use), out evict-first (write-once),
// lab8 via __ldcg (L2-resident from reduce's __stcg; skip L1).
// ---------------------------------------------------------------------------
__global__ void __launch_bounds__(256) apply_packed_k(const float4* __restrict__ tex4,
                                                      float4* __restrict__ out4,
                                                      int n4) {
    __shared__ float sd[NUM_LABELS];
    if (threadIdx.x < NUM_LABELS) sd[threadIdx.x] = g_delta[threadIdx.x];
    __syncthreads();

    const unsigned int* lab8w = (const unsigned int*)g_lab8;
    int i0 = blockIdx.x * 512 + threadIdx.x;
    int i1 = i0 + 256;

    if (i1 < n4) {
        const float4 ta = __ldcs(&tex4[i0]);
        const float4 tb = __ldcs(&tex4[i1]);
        const unsigned int la = __ldcg(&lab8w[i0]);
        const unsigned int lb = __ldcg(&lab8w[i1]);
        float4 oa, ob;
        oa.x = ta.x - sd[la & 0xFF];
        oa.y = ta.y - sd[(la >> 8) & 0xFF];
        oa.z = ta.z - sd[(la >> 16) & 0xFF];
        oa.w = ta.w - sd[la >> 24];
        ob.x = tb.x - sd[lb & 0xFF];
        ob.y = tb.y - sd[(lb >> 8) & 0xFF];
        ob.z = tb.z - sd[(lb >> 16) & 0xFF];
        ob.w = tb.w - sd[lb >> 24];
        __stcs(&out4[i0], oa);
        __stcs(&out4[i1], ob);
    } else if (i0 < n4) {
        const float4 t = __ldcs(&tex4[i0]);
        const unsigned int l = __ldcg(&lab8w[i0]);
        float4 o;
        o.x = t.x - sd[l & 0xFF];
        o.y = t.y - sd[(l >> 8) & 0xFF];
        o.z = t.z - sd[(l >> 16) & 0xFF];
        o.w = t.w - sd[l >> 24];
        __stcs(&out4[i0], o);
    }
}

// ---------------------------------------------------------------------------
// Fallback path (n not 4-divisible or > MAXN): scalar, shared-atomic
// ---------------------------------------------------------------------------
__global__ void zero_k() {
    int i = threadIdx.x;
    if (i < NUM_LABELS) { g_sums[i] = 0.0f; g_cnts[i] = 0.0f; }
}

__global__ void __launch_bounds__(256) reduce_scalar_k(const float* __restrict__ tex,
                                                       const int*  __restrict__ lab,
                                                       int n) {
    __shared__ float2 accw[8][NUM_LABELS];
    const int w = threadIdx.x >> 5;
    for (int i = threadIdx.x; i < 8 * NUM_LABELS; i += 256)
        (&accw[0][0])[i] = make_float2(0.0f, 0.0f);
    __syncthreads();
    int i = blockIdx.x * 256 + threadIdx.x;
    const int stride = gridDim.x * 256;
    for (; i < n; i += stride) {
        atomicAdd(&accw[w][lab[i]].x, tex[i]);
        atomicAdd(&accw[w][lab[i]].y, 1.0f);
    }
    __syncthreads();
    for (int l = threadIdx.x; l < NUM_LABELS; l += 256) {
        float s = 0.0f, c = 0.0f;
        #pragma unroll
        for (int ww = 0; ww < 8; ww++) { s += accw[ww][l].x; c += accw[ww][l].y; }
        atomicAdd(&g_sums[l], s);
        atomicAdd(&g_cnts[l], c);
    }
}

__global__ void delta_k(const float* __restrict__ inten) {
    int l = threadIdx.x;
    if (l < NUM_LABELS) {
        float m = g_sums[l] / fmaxf(g_cnts[l], 1.0f);
        g_delta[l] = (l > 0) ? (m - inten[l]) : 0.0f;
    }
}

__global__ void __launch_bounds__(256) apply_scalar_k(const float* __restrict__ tex,
                                                      const int*  __restrict__ lab,
                                                      float* __restrict__ out,
                                                      int n) {
    __shared__ float sd[NUM_LABELS];
    if (threadIdx.x < NUM_LABELS) sd[threadIdx.x] = g_delta[threadIdx.x];
    __syncthreads();
    int i = blockIdx.x * 256 + threadIdx.x;
    if (i < n) out[i] = tex[i] - sd[lab[i]];
}

// ---------------------------------------------------------------------------
extern "C" void kernel_launch(void* const* d_in, const int* in_sizes, int n_in,
                              void* d_out, int out_size) {
    const float* tex   = (const float*)d_in[0];
    const int*   lab   = (const int*)  d_in[1];
    const float* inten = (const float*)d_in[2];
    float* out = (float*)d_out;

    const int n  = in_sizes[0];
    const int n4 = n >> 2;
    const bool fast = ((n & 3) == 0) && (n <= MAXN) && (n4 >= RED_CTAS * RED_THREADS);

    if (fast) {
        static int smem_set = 0;   // host-side one-time config
        const int smem_bytes = NUM_LABELS * RED_THREADS * (int)sizeof(float); // 64KB
        if (!smem_set) {
            cudaFuncSetAttribute(reduce_k, cudaFuncAttributeMaxDynamicSharedMemorySize,
                                 smem_bytes);
            smem_set = 1;
        }
        reduce_k<<<RED_CTAS, RED_THREADS, smem_bytes>>>((const float4*)tex,
                                                        (const int4*)lab, n4);
        delta_fast_k<<<NUM_LABELS, 128>>>(inten);
        int app_blocks = (n4 + 511) / 512;
        apply_packed_k<<<app_blocks, 256>>>((const float4*)tex, (float4*)out, n4);
    } else {
        zero_k<<<1, 64>>>();
        reduce_scalar_k<<<1184, 256>>>(tex, lab, n);
        delta_k<<<1, 64>>>(inten);
        int app_blocks = (n + 255) / 256;
        apply_scalar_k<<<app_blocks, 256>>>(tex, lab, out, n);
    }
}